// round 10
// baseline (speedup 1.0000x reference)
#include <cuda_runtime.h>
#include <cstdint>

// Problem constants
constexpr int KC = 5, PC = 2, BC = 2, NC = 8, HC = 512, WC = 512;

// Full-width tiles: 8 rows x 512 cols, processed as two 4-row passes.
// Each pass's core-plane read is one CONTIGUOUS 8KB block per k -> maximal
// DRAM page locality. Taller tile halves per-tile fixed costs (barriers,
// commit/wait, store drain) and cuts staged halo from 2.0x to 1.5x.
constexpr int TH = 8;
constexpr int SWP = 520;             // padded row pitch (floats), 16B aligned
constexpr int NT = 512;              // threads per CTA
constexpr int TILES_Y = HC / TH;     // 64 row-tiles
constexpr int N_TILES = TILES_Y * BC * NC;   // 1024
constexpr int GRID = 304;            // 152 SM x 2 CTAs, persistent
constexpr int SH = TH + 2 * PC;      // 12 staged rows
constexpr int SBUF = SH * SWP;       // 6240 floats per buffer

// cp.async 4B with zero-fill when !ok (src-size 0 -> no global read, zeros)
__device__ __forceinline__ void cp4(uint32_t dst, const float* src, bool ok) {
    asm volatile("cp.async.ca.shared.global [%0], [%1], 4, %2;\n"
                 :: "r"(dst), "l"(src), "r"(ok ? 4 : 0));
}

__global__ __launch_bounds__(NT, 2)
void kconv_kernel(const float* __restrict__ frames,
                  const float* __restrict__ core,
                  const float* __restrict__ Wt,
                  float* __restrict__ out)
{
    __shared__ float s[2][SBUF];

    const size_t plane = (size_t)HC * WC;
    const uint32_t sbase = (uint32_t)__cvta_generic_to_shared(&s[0][0]);

    // ---- async stage of one padded 12x520 frame strip into a smem buffer ----
    auto stage = [&](int t, int buf) {
        const int ty = (t & (TILES_Y - 1)) * TH;
        const int z  = t >> 6;                      // b*N + n
        const float* fb = frames + (size_t)z * plane;
        const uint32_t sb = sbase + (uint32_t)buf * (SBUF * 4);
        #pragma unroll
        for (int it = 0; it < 13; ++it) {
            const int idx = threadIdx.x + it * NT;
            if (idx < SBUF) {
                const int r = idx / SWP;
                const int c = idx - r * SWP;
                const int gy = ty + r - PC;
                const int gx = c - PC;
                const bool ok = (unsigned)gy < (unsigned)HC && (unsigned)gx < (unsigned)WC;
                const float* gp = ok ? (fb + (size_t)gy * WC + gx) : fb;
                cp4(sb + (uint32_t)idx * 4, gp, ok);
            }
        }
        asm volatile("cp.async.commit_group;\n");
    };

    // Thread -> output mapping: per pass, 4 rows x 128 float4-groups.
    const int row0 = threadIdx.x >> 7;           // 0..3
    const int xx   = (threadIdx.x & 127) << 2;   // 0..508

    int t = blockIdx.x;
    if (t >= N_TILES) return;
    stage(t, 0);
    int buf = 0;

    while (t < N_TILES) {
        const int tn = t + GRID;                 // static strided schedule

        // make current buffer visible, then prefetch the next tile into the
        // other buffer (overlaps the compute below)
        asm volatile("cp.async.wait_group 0;\n");
        __syncthreads();
        if (tn < N_TILES) stage(tn, buf ^ 1);

        const int ty = (t & (TILES_Y - 1)) * TH;
        const int z  = t >> 6;
        const float* cbase = core + (size_t)z * (KC * KC) * plane;
        const float* wbase = Wt  + (size_t)z * plane;
        float*       obase = out + (size_t)z * plane;
        const float* sb = &s[buf][0];

        // ---- two 4-row passes over the tile ----
        #pragma unroll
        for (int pass = 0; pass < 2; ++pass) {
            const int row = row0 + pass * 4;     // 0..7
            const int gy  = ty + row;
            const size_t pix = (size_t)gy * WC + xx;

            // W: read-once, issue early so its latency overlaps the burst
            const float4 wv = __ldcs(reinterpret_cast<const float4*>(wbase + pix));

            // Preload the 5x8 frame window (pure LDS phase)
            float w[KC][8];
            #pragma unroll
            for (int i = 0; i < KC; ++i) {
                const float* srow = sb + (row + i) * SWP + xx;
                const float4 a  = *reinterpret_cast<const float4*>(srow);
                const float4 bq = *reinterpret_cast<const float4*>(srow + 4);
                w[i][0] = a.x;  w[i][1] = a.y;  w[i][2] = a.z;  w[i][3] = a.w;
                w[i][4] = bq.x; w[i][5] = bq.y; w[i][6] = bq.z; w[i][7] = bq.w;
            }

            // Pure LDG->FMA stream: per k, the CTA pass reads one contiguous
            // 8KB block of the core plane.
            float acc0 = 0.f, acc1 = 0.f, acc2 = 0.f, acc3 = 0.f;
            #pragma unroll
            for (int i = 0; i < KC; ++i) {
                #pragma unroll
                for (int j = 0; j < KC; ++j) {
                    const int k = i * KC + j;
                    const float4 cv = __ldcs(
                        reinterpret_cast<const float4*>(cbase + (size_t)k * plane + pix));
                    acc0 = fmaf(cv.x, w[i][j + 0], acc0);
                    acc1 = fmaf(cv.y, w[i][j + 1], acc1);
                    acc2 = fmaf(cv.z, w[i][j + 2], acc2);
                    acc3 = fmaf(cv.w, w[i][j + 3], acc3);
                }
            }

            float4 o;
            o.x = acc0 * wv.x;
            o.y = acc1 * wv.y;
            o.z = acc2 * wv.z;
            o.w = acc3 * wv.w;
            __stcs(reinterpret_cast<float4*>(obase + pix), o);
        }

        t = tn;
        buf ^= 1;
    }
}

extern "C" void kernel_launch(void* const* d_in, const int* in_sizes, int n_in,
                              void* d_out, int out_size)
{
    const float* frames = (const float*)d_in[0];
    const float* core   = (const float*)d_in[1];
    const float* Wt     = (const float*)d_in[2];
    float* out          = (float*)d_out;

    kconv_kernel<<<GRID, NT>>>(frames, core, Wt, out);
}

// round 11
// speedup vs baseline: 1.0088x; 1.0088x over previous
#include <cuda_runtime.h>
#include <cstdint>

// Problem constants
constexpr int KC = 5, PC = 2, BC = 2, NC = 8, HC = 512, WC = 512;

// Rolling-ring full-width kernel:
//  - 304 persistent CTAs = 16 planes x 19 CTAs; each CTA owns a contiguous
//    vertical strip of one (b,n) plane (6 or 7 groups of 4 rows).
//  - 16-row smem ring (slot = image_row & 15): each frame row staged ONCE
//    per strip (1.15x frames traffic vs 2.0x for independent tiles).
//  - Prefetch next 4 rows (disjoint ring slots) overlaps current compute.
//  - Compute: per k, one contiguous 8KB core-plane block per group (maximal
//    DRAM page locality), register 5x8 window, __ldcs/__stcs streams.
constexpr int NT  = 512;
constexpr int CPP = 19;               // CTAs per plane
constexpr int GRID = 16 * CPP;        // 304
constexpr int SWP = 520;              // ring row pitch (floats), 2080B (16B-mult)
constexpr int RING = 16;              // ring rows (power of two)

// cp.async 4B with zero-fill when !ok (src-size 0 -> no global read, zeros)
__device__ __forceinline__ void cp4(uint32_t dst, const float* src, bool ok) {
    asm volatile("cp.async.ca.shared.global [%0], [%1], 4, %2;\n"
                 :: "r"(dst), "l"(src), "r"(ok ? 4 : 0));
}

__global__ __launch_bounds__(NT, 2)
void kconv_kernel(const float* __restrict__ frames,
                  const float* __restrict__ core,
                  const float* __restrict__ Wt,
                  float* __restrict__ out)
{
    __shared__ float ring[RING][SWP];   // 33,280 B -> 2 CTAs/SM

    const size_t plane = (size_t)HC * WC;
    const int cta = blockIdx.x;
    const int z   = cta / CPP;          // plane (b*N + n)
    const int sgi = cta - z * CPP;      // strip index within plane
    // 128 row-groups per plane split 19-ways: first 14 CTAs get 7, rest 6
    const int g0 = (sgi < 14) ? sgi * 7 : 98 + (sgi - 14) * 6;
    const int ng = (sgi < 14) ? 7 : 6;

    const float* fb    = frames + (size_t)z * plane;
    const float* cbase = core   + (size_t)z * (KC * KC) * plane;
    const float* wbase = Wt     + (size_t)z * plane;
    float*       obase = out    + (size_t)z * plane;

    const uint32_t sb = (uint32_t)__cvta_generic_to_shared(&ring[0][0]);

    // stage image rows [r0, r0+nr) into ring slots (row & 15); cols -2..517
    // with zero-fill outside the image. One cp.async group per call.
    auto stage_rows = [&](int r0, int nr) {
        const int total = nr * SWP;
        for (int it = 0; it * NT < total; ++it) {
            const int idx = threadIdx.x + it * NT;
            if (idx < total) {
                const int r  = idx / SWP;
                const int cc = idx - r * SWP;
                const int gy = r0 + r;
                const int gx = cc - PC;
                const bool ok = (unsigned)gy < (unsigned)HC && (unsigned)gx < (unsigned)WC;
                const float* gp = ok ? (fb + (size_t)gy * WC + gx) : fb;
                const uint32_t dst = sb + (uint32_t)((((gy & (RING - 1)) * SWP) + cc) * 4);
                cp4(dst, gp, ok);
            }
        }
        asm volatile("cp.async.commit_group;\n");
    };

    // Thread -> output mapping: 4 rows x 128 float4-groups per group.
    const int row0 = threadIdx.x >> 7;           // 0..3
    const int xx   = (threadIdx.x & 127) << 2;   // 0..508

    int ty = g0 * 4;
    stage_rows(ty - PC, 8);                      // initial window rows ty-2..ty+5

    for (int g = 0; g < ng; ++g, ty += 4) {
        // prefetch the next group's 4 new rows (disjoint ring slots), or an
        // empty group on the last iteration to keep wait_group math uniform
        if (g + 1 < ng) stage_rows(ty + 6, 4);
        else asm volatile("cp.async.commit_group;\n");
        // wait for everything except the group just committed -> the rows
        // needed for THIS group are complete
        asm volatile("cp.async.wait_group 1;\n");
        __syncthreads();

        const int gy = ty + row0;
        const size_t pix = (size_t)gy * WC + xx;

        // W: read-once, issue early so its latency overlaps the core burst
        const float4 wv = __ldcs(reinterpret_cast<const float4*>(wbase + pix));

        // Preload the 5x8 frame window from ring slots (pure LDS phase)
        float w[KC][8];
        #pragma unroll
        for (int i = 0; i < KC; ++i) {
            const float* srow = &ring[(gy + i - PC) & (RING - 1)][xx];
            const float4 a  = *reinterpret_cast<const float4*>(srow);
            const float4 bq = *reinterpret_cast<const float4*>(srow + 4);
            w[i][0] = a.x;  w[i][1] = a.y;  w[i][2] = a.z;  w[i][3] = a.w;
            w[i][4] = bq.x; w[i][5] = bq.y; w[i][6] = bq.z; w[i][7] = bq.w;
        }

        // Pure LDG->FMA stream: per k, this group reads one contiguous 8KB
        // block of the core plane.
        float acc0 = 0.f, acc1 = 0.f, acc2 = 0.f, acc3 = 0.f;
        #pragma unroll
        for (int i = 0; i < KC; ++i) {
            #pragma unroll
            for (int j = 0; j < KC; ++j) {
                const int k = i * KC + j;
                const float4 cv = __ldcs(
                    reinterpret_cast<const float4*>(cbase + (size_t)k * plane + pix));
                acc0 = fmaf(cv.x, w[i][j + 0], acc0);
                acc1 = fmaf(cv.y, w[i][j + 1], acc1);
                acc2 = fmaf(cv.z, w[i][j + 2], acc2);
                acc3 = fmaf(cv.w, w[i][j + 3], acc3);
            }
        }

        float4 o;
        o.x = acc0 * wv.x;
        o.y = acc1 * wv.y;
        o.z = acc2 * wv.z;
        o.w = acc3 * wv.w;
        __stcs(reinterpret_cast<float4*>(obase + pix), o);
        // No trailing barrier needed: next iteration's prefetch writes ring
        // slots (ty+10..ty+13) & 15, disjoint mod 16 from this group's read
        // window (ty-2..ty+5) and the previous one's.
    }
}

extern "C" void kernel_launch(void* const* d_in, const int* in_sizes, int n_in,
                              void* d_out, int out_size)
{
    const float* frames = (const float*)d_in[0];
    const float* core   = (const float*)d_in[1];
    const float* Wt     = (const float*)d_in[2];
    float* out          = (float*)d_out;

    kconv_kernel<<<GRID, NT>>>(frames, core, Wt, out);
}